// round 3
// baseline (speedup 1.0000x reference)
#include <cuda_runtime.h>
#include <cuda_bf16.h>
#include <math.h>

// Problem-shape upper bounds (static scratch sizing)
#define MAXN 100000
#define MAXE 3200000
#define MAXET (MAXE + MAXN)
#define FIN 128
#define HD1 64
#define HD2 16
#define NCLS 10

#define CDIV(a,b) (((a)+(b)-1)/(b))

// ---------------- scratch (device globals; no allocation allowed) ----------
__device__ __align__(128) int   g_src[MAXET];
__device__ __align__(128) int   g_dst[MAXET];
__device__ __align__(128) float g_h1[(size_t)MAXN * HD1];
__device__ __align__(128) float g_o1[(size_t)MAXN * HD1];
__device__ __align__(128) float g_h2[(size_t)MAXN * HD2];
__device__ __align__(128) float g_o2[(size_t)MAXN * HD2];
__device__ __align__(128) float g_ssrc[MAXN];
__device__ __align__(128) float g_sdst[MAXN];
__device__ __align__(128) float g_m[MAXN];
__device__ __align__(128) float g_z[MAXN];
__device__ __align__(128) float g_p[MAXET];
__device__ int g_is64;

// ---------------- helpers --------------------------------------------------
__device__ __forceinline__ void red_add_v4(float* p, float a, float b, float c, float d) {
    asm volatile("red.global.add.v4.f32 [%0], {%1,%2,%3,%4};"
                 :: "l"(p), "f"(a), "f"(b), "f"(c), "f"(d) : "memory");
}

__device__ __forceinline__ void atomic_max_f(float* addr, float v) {
    if (v >= 0.f) atomicMax((int*)addr, __float_as_int(v));
    else          atomicMin((unsigned int*)addr, __float_as_uint(v));
}

// ---------------- edge index prep ------------------------------------------
__global__ void detect_kernel(const void* ei, int E, int N) {
    if (blockIdx.x == 0 && threadIdx.x == 0) {
        const long long* p = (const long long*)ei;
        int n = 2 * E; if (n > 64) n = 64;
        int ok = 1;
        for (int i = 0; i < n; i++) {
            long long v = p[i];
            if (v < 0 || v >= (long long)N) { ok = 0; break; }
        }
        g_is64 = ok;
    }
}

__global__ void convert_kernel(const void* ei, int E, int N) {
    int e = blockIdx.x * blockDim.x + threadIdx.x;
    int tot = E + N;
    if (e >= tot) return;
    if (e < E) {
        if (g_is64) {
            const long long* p = (const long long*)ei;
            g_src[e] = (int)p[e];
            g_dst[e] = (int)p[(size_t)E + e];
        } else {
            const int* p = (const int*)ei;
            g_src[e] = p[e];
            g_dst[e] = p[E + e];
        }
    } else {            // self-loops
        g_src[e] = e - E;
        g_dst[e] = e - E;
    }
}

// ---------------- init -----------------------------------------------------
__global__ void init_mz(int N) {
    int i = blockIdx.x * blockDim.x + threadIdx.x;
    if (i < N) { g_m[i] = __int_as_float(0xFF800000); g_z[i] = 0.f; }
}
__global__ void zero_o1(int n) {
    int i = blockIdx.x * blockDim.x + threadIdx.x;
    if (i < n) g_o1[i] = 0.f;
}
__global__ void zero_o2(int n) {
    int i = blockIdx.x * blockDim.x + threadIdx.x;
    if (i < n) g_o2[i] = 0.f;
}

// ---------------- GEMM1: h1 = x @ W1  (M=N, K=128, N=64) -------------------
__global__ void gemm1_kernel(const float* __restrict__ x, const float* __restrict__ W, int N) {
    __shared__ float As[32][68];  // [k][row]
    __shared__ float Bs[32][68];  // [k][col]
    int tid = threadIdx.x;                 // 256 threads
    int ty = tid >> 4, tx = tid & 15;
    int row0 = blockIdx.x * 64;
    float acc[4][4] = {};
    for (int kt = 0; kt < FIN; kt += 32) {
        #pragma unroll
        for (int i = 0; i < 8; i++) {       // A: 64 rows x 32 k
            int l = tid + i * 256;
            int k = l & 31, r = l >> 5;
            int node = row0 + r;
            As[k][r] = (node < N) ? x[(size_t)node * FIN + kt + k] : 0.f;
        }
        #pragma unroll
        for (int i = 0; i < 8; i++) {       // B: 32 k x 64 col
            int l = tid + i * 256;
            int col = l & 63, k = l >> 6;
            Bs[k][col] = W[(kt + k) * HD1 + col];
        }
        __syncthreads();
        #pragma unroll
        for (int k = 0; k < 32; k++) {
            float a[4], b[4];
            #pragma unroll
            for (int i = 0; i < 4; i++) a[i] = As[k][ty * 4 + i];
            #pragma unroll
            for (int j = 0; j < 4; j++) b[j] = Bs[k][tx * 4 + j];
            #pragma unroll
            for (int i = 0; i < 4; i++)
                #pragma unroll
                for (int j = 0; j < 4; j++) acc[i][j] += a[i] * b[j];
        }
        __syncthreads();
    }
    #pragma unroll
    for (int i = 0; i < 4; i++) {
        int node = row0 + ty * 4 + i;
        if (node < N) {
            #pragma unroll
            for (int j = 0; j < 4; j++)
                g_h1[(size_t)node * HD1 + tx * 4 + j] = acc[i][j];
        }
    }
}

// ---------------- s1 = h1 @ a_src / a_dst (warp per node) ------------------
__global__ void s1_kernel(const float* __restrict__ a_src, const float* __restrict__ a_dst, int N) {
    int w = (blockIdx.x * blockDim.x + threadIdx.x) >> 5;
    int lane = threadIdx.x & 31;
    if (w >= N) return;
    const float* h = g_h1 + (size_t)w * HD1;
    float v0 = h[lane], v1 = h[lane + 32];
    float ss = v0 * a_src[lane] + v1 * a_src[lane + 32];
    float sd = v0 * a_dst[lane] + v1 * a_dst[lane + 32];
    #pragma unroll
    for (int o = 16; o; o >>= 1) {
        ss += __shfl_down_sync(0xFFFFFFFFu, ss, o);
        sd += __shfl_down_sync(0xFFFFFFFFu, sd, o);
    }
    if (lane == 0) { g_ssrc[w] = ss; g_sdst[w] = sd; }
}

// ---------------- edge passes ----------------------------------------------
__global__ void epass1(int Etot) {   // segment max
    int e = blockIdx.x * blockDim.x + threadIdx.x;
    if (e >= Etot) return;
    int s = g_src[e], d = g_dst[e];
    float v = g_ssrc[s] + g_sdst[d];
    v = v > 0.f ? v : 0.2f * v;
    atomic_max_f(&g_m[d], v);
}

__global__ void epass2(int Etot) {   // p = exp(e - m), z += p
    int e = blockIdx.x * blockDim.x + threadIdx.x;
    if (e >= Etot) return;
    int s = g_src[e], d = g_dst[e];
    float v = g_ssrc[s] + g_sdst[d];
    v = v > 0.f ? v : 0.2f * v;
    float p = __expf(v - g_m[d]);
    g_p[e] = p;
    atomicAdd(&g_z[d], p);
}

// layer-1 scatter: 8 threads per edge, 64 features
__global__ void epass3_h64(int Etot) {
    int gid = blockIdx.x * blockDim.x + threadIdx.x;
    int e = gid >> 3, lane = gid & 7;
    if (e >= Etot) return;
    int s = g_src[e], d = g_dst[e];
    float alpha = __fdividef(g_p[e], g_z[d]);
    const float4* hs = (const float4*)(g_h1 + (size_t)s * HD1) + lane * 2;
    float4 v0 = hs[0], v1 = hs[1];
    float* ob = g_o1 + (size_t)d * HD1 + lane * 8;
    red_add_v4(ob,     v0.x * alpha, v0.y * alpha, v0.z * alpha, v0.w * alpha);
    red_add_v4(ob + 4, v1.x * alpha, v1.y * alpha, v1.z * alpha, v1.w * alpha);
}

// layer-2 scatter: 4 threads per edge, 16 features
__global__ void epass3_h16(int Etot) {
    int gid = blockIdx.x * blockDim.x + threadIdx.x;
    int e = gid >> 2, lane = gid & 3;
    if (e >= Etot) return;
    int s = g_src[e], d = g_dst[e];
    float alpha = __fdividef(g_p[e], g_z[d]);
    const float4* hs = (const float4*)(g_h2 + (size_t)s * HD2);
    float4 v = hs[lane];
    float* ob = g_o2 + (size_t)d * HD2 + lane * 4;
    red_add_v4(ob, v.x * alpha, v.y * alpha, v.z * alpha, v.w * alpha);
}

// ---------------- GEMM2: h2 = relu(o1 + b1) @ W2 (K=64, N=16) --------------
__global__ void gemm2_kernel(const float* __restrict__ W2, const float* __restrict__ b1, int N) {
    __shared__ float Os[128][65];
    __shared__ float Ws[64][17];
    int tid = threadIdx.x;                 // 128 threads
    int node0 = blockIdx.x * 128;
    for (int i = tid; i < HD1 * HD2; i += 128) Ws[i >> 4][i & 15] = W2[i];
    for (int i = tid; i < 128 * HD1; i += 128) {
        int r = i >> 6, k = i & 63;
        int node = node0 + r;
        Os[r][k] = (node < N) ? fmaxf(g_o1[(size_t)node * HD1 + k] + __ldg(&b1[k]), 0.f) : 0.f;
    }
    __syncthreads();
    int node = node0 + tid;
    if (node >= N) return;
    float acc[16] = {};
    #pragma unroll 4
    for (int k = 0; k < HD1; k++) {
        float v = Os[tid][k];
        #pragma unroll
        for (int j = 0; j < HD2; j++) acc[j] += v * Ws[k][j];
    }
    float4* out = (float4*)(g_h2 + (size_t)node * HD2);
    out[0] = make_float4(acc[0], acc[1], acc[2], acc[3]);
    out[1] = make_float4(acc[4], acc[5], acc[6], acc[7]);
    out[2] = make_float4(acc[8], acc[9], acc[10], acc[11]);
    out[3] = make_float4(acc[12], acc[13], acc[14], acc[15]);
}

// ---------------- s2 (thread per node, 16 feats) ---------------------------
__global__ void s2_kernel(const float* __restrict__ a_src, const float* __restrict__ a_dst, int N) {
    int n = blockIdx.x * blockDim.x + threadIdx.x;
    if (n >= N) return;
    const float* h = g_h2 + (size_t)n * HD2;
    float ss = 0.f, sd = 0.f;
    #pragma unroll
    for (int i = 0; i < HD2; i++) {
        float v = h[i];
        ss += v * __ldg(&a_src[i]);
        sd += v * __ldg(&a_dst[i]);
    }
    g_ssrc[n] = ss;
    g_sdst[n] = sd;
}

// ---------------- classifier + log_softmax ---------------------------------
__global__ void final_kernel(const float* __restrict__ b2, const float* __restrict__ Wc,
                             const float* __restrict__ bc, float* __restrict__ out, int N) {
    __shared__ float Wcs[HD2 * NCLS];
    __shared__ float bcs[NCLS];
    __shared__ float b2s[HD2];
    int tid = threadIdx.x;                 // 128 threads
    for (int i = tid; i < HD2 * NCLS; i += 128) Wcs[i] = Wc[i];   // grid-stride: 160 > 128
    if (tid < NCLS) bcs[tid] = bc[tid];
    if (tid < HD2) b2s[tid] = b2[tid];
    __syncthreads();
    int n = blockIdx.x * 128 + tid;
    if (n >= N) return;
    float h[HD2];
    const float4* hv = (const float4*)(g_o2 + (size_t)n * HD2);
    #pragma unroll
    for (int i = 0; i < 4; i++) {
        float4 v = hv[i];
        h[i * 4 + 0] = v.x + b2s[i * 4 + 0];
        h[i * 4 + 1] = v.y + b2s[i * 4 + 1];
        h[i * 4 + 2] = v.z + b2s[i * 4 + 2];
        h[i * 4 + 3] = v.w + b2s[i * 4 + 3];
    }
    float logits[NCLS];
    #pragma unroll
    for (int c = 0; c < NCLS; c++) {
        float acc = bcs[c];
        #pragma unroll
        for (int k = 0; k < HD2; k++) acc += h[k] * Wcs[k * NCLS + c];
        logits[c] = acc;
    }
    float mx = logits[0];
    #pragma unroll
    for (int c = 1; c < NCLS; c++) mx = fmaxf(mx, logits[c]);
    float sum = 0.f;
    #pragma unroll
    for (int c = 0; c < NCLS; c++) sum += __expf(logits[c] - mx);
    float lse = mx + logf(sum);
    #pragma unroll
    for (int c = 0; c < NCLS; c++) out[(size_t)n * NCLS + c] = logits[c] - lse;
}

// ---------------- launch ----------------------------------------------------
extern "C" void kernel_launch(void* const* d_in, const int* in_sizes, int n_in,
                              void* d_out, int out_size) {
    const float* x   = (const float*)d_in[0];
    const void*  ei  = d_in[1];
    const float* W1  = (const float*)d_in[2];
    const float* a1s = (const float*)d_in[3];
    const float* a1d = (const float*)d_in[4];
    const float* b1  = (const float*)d_in[5];
    const float* W2  = (const float*)d_in[6];
    const float* a2s = (const float*)d_in[7];
    const float* a2d = (const float*)d_in[8];
    const float* b2  = (const float*)d_in[9];
    const float* Wc  = (const float*)d_in[10];
    const float* bc  = (const float*)d_in[11];
    float* out = (float*)d_out;

    int N = in_sizes[0] / FIN;
    int E = in_sizes[1] / 2;
    int Etot = E + N;

    detect_kernel<<<1, 32>>>(ei, E, N);
    convert_kernel<<<CDIV(Etot, 256), 256>>>(ei, E, N);

    // ---- layer 1 ----
    init_mz<<<CDIV(N, 256), 256>>>(N);
    zero_o1<<<CDIV(N * HD1, 256), 256>>>(N * HD1);
    gemm1_kernel<<<CDIV(N, 64), 256>>>(x, W1, N);
    s1_kernel<<<CDIV(N * 32, 256), 256>>>(a1s, a1d, N);
    epass1<<<CDIV(Etot, 256), 256>>>(Etot);
    epass2<<<CDIV(Etot, 256), 256>>>(Etot);
    epass3_h64<<<CDIV(Etot * 8, 256), 256>>>(Etot);

    // ---- layer 2 ----
    init_mz<<<CDIV(N, 256), 256>>>(N);
    zero_o2<<<CDIV(N * HD2, 256), 256>>>(N * HD2);
    gemm2_kernel<<<CDIV(N, 128), 128>>>(W2, b1, N);
    s2_kernel<<<CDIV(N, 256), 256>>>(a2s, a2d, N);
    epass1<<<CDIV(Etot, 256), 256>>>(Etot);
    epass2<<<CDIV(Etot, 256), 256>>>(Etot);
    epass3_h16<<<CDIV(Etot * 4, 256), 256>>>(Etot);

    // ---- classifier ----
    final_kernel<<<CDIV(N, 128), 128>>>(b2, Wc, bc, out, N);
}

// round 5
// speedup vs baseline: 2.0550x; 2.0550x over previous
#include <cuda_runtime.h>
#include <cuda_bf16.h>
#include <math.h>

#define MAXN 100000
#define MAXE 3200000
#define MAXET (MAXE + MAXN)
#define FIN 128
#define HD1 64
#define HD2 16
#define NCLS 10
#define CDIV(a,b) (((a)+(b)-1)/(b))

// ---------------- scratch ---------------------------------------------------
__device__ __align__(128) int   g_src[MAXET];
__device__ __align__(128) int   g_dst[MAXET];
__device__ __align__(128) int   g_esrc[MAXET];     // CSR column (src) array
__device__ __align__(128) int   g_deg[MAXN];
__device__ __align__(128) int   g_rowptr[MAXN + 1];
__device__ __align__(128) int   g_cur[MAXN];
__device__ __align__(128) int   g_bsum[512];
__device__ __align__(128) float g_h1[(size_t)MAXN * HD1];
__device__ __align__(128) float g_t1[(size_t)MAXN * HD1];  // relu(o1/z + b1)
__device__ __align__(128) float g_h2[(size_t)MAXN * HD2];
__device__ __align__(128) float g_o2[(size_t)MAXN * HD2];  // normalized layer-2 agg
__device__ __align__(128) float g_ssrc[MAXN];
__device__ __align__(128) float g_sdst[MAXN];
__device__ int g_is64;

// ---------------- edge prep -------------------------------------------------
__global__ void detect_kernel(const void* ei, int E, int N) {
    if (blockIdx.x == 0 && threadIdx.x == 0) {
        const long long* p = (const long long*)ei;
        int n = 2 * E; if (n > 64) n = 64;
        int ok = 1;
        for (int i = 0; i < n; i++) {
            long long v = p[i];
            if (v < 0 || v >= (long long)N) { ok = 0; break; }
        }
        g_is64 = ok;
    }
}

__global__ void zero_deg(int N) {
    int i = blockIdx.x * blockDim.x + threadIdx.x;
    if (i < N) g_deg[i] = 0;
}

// convert + degree histogram fused
__global__ void convert_kernel(const void* ei, int E, int N) {
    int e = blockIdx.x * blockDim.x + threadIdx.x;
    int tot = E + N;
    if (e >= tot) return;
    int s, d;
    if (e < E) {
        if (g_is64) {
            const long long* p = (const long long*)ei;
            s = (int)p[e];
            d = (int)p[(size_t)E + e];
        } else {
            const int* p = (const int*)ei;
            s = p[e];
            d = p[E + e];
        }
    } else {            // self-loops
        s = e - E; d = e - E;
    }
    g_src[e] = s;
    g_dst[e] = d;
    atomicAdd(&g_deg[d], 1);
}

// ---------------- prefix sum (3-phase block scan) ---------------------------
__global__ void scanA(int N) {
    __shared__ int sm[256];
    int tid = threadIdx.x;
    int i = blockIdx.x * 256 + tid;
    int v = (i < N) ? g_deg[i] : 0;
    sm[tid] = v;
    __syncthreads();
    #pragma unroll
    for (int o = 1; o < 256; o <<= 1) {
        int t = (tid >= o) ? sm[tid - o] : 0;
        __syncthreads();
        sm[tid] += t;
        __syncthreads();
    }
    if (i < N) g_rowptr[i] = sm[tid] - v;      // block-local exclusive
    if (tid == 255) g_bsum[blockIdx.x] = sm[255];
}

__global__ void scanB(int nb, int N, int Etot) {
    __shared__ int sm[512];
    int tid = threadIdx.x;
    int v = (tid < nb) ? g_bsum[tid] : 0;
    sm[tid] = v;
    __syncthreads();
    #pragma unroll
    for (int o = 1; o < 512; o <<= 1) {
        int t = (tid >= o) ? sm[tid - o] : 0;
        __syncthreads();
        sm[tid] += t;
        __syncthreads();
    }
    if (tid < nb) g_bsum[tid] = sm[tid] - v;   // exclusive block offsets
    if (tid == 0) g_rowptr[N] = Etot;
}

__global__ void scanC(int N) {
    int i = blockIdx.x * 256 + threadIdx.x;
    if (i < N) {
        int v = g_rowptr[i] + g_bsum[blockIdx.x];
        g_rowptr[i] = v;
        g_cur[i] = v;
    }
}

__global__ void scatter_kernel(int Etot) {
    int e = blockIdx.x * blockDim.x + threadIdx.x;
    if (e >= Etot) return;
    int pos = atomicAdd(&g_cur[g_dst[e]], 1);
    g_esrc[pos] = g_src[e];
}

// ---------------- GEMM1: h1 = x @ W1 ----------------------------------------
__global__ void gemm1_kernel(const float* __restrict__ x, const float* __restrict__ W, int N) {
    __shared__ float As[32][68];
    __shared__ float Bs[32][68];
    int tid = threadIdx.x;
    int ty = tid >> 4, tx = tid & 15;
    int row0 = blockIdx.x * 64;
    float acc[4][4] = {};
    for (int kt = 0; kt < FIN; kt += 32) {
        #pragma unroll
        for (int i = 0; i < 8; i++) {
            int l = tid + i * 256;
            int k = l & 31, r = l >> 5;
            int node = row0 + r;
            As[k][r] = (node < N) ? x[(size_t)node * FIN + kt + k] : 0.f;
        }
        #pragma unroll
        for (int i = 0; i < 8; i++) {
            int l = tid + i * 256;
            int col = l & 63, k = l >> 6;
            Bs[k][col] = W[(kt + k) * HD1 + col];
        }
        __syncthreads();
        #pragma unroll
        for (int k = 0; k < 32; k++) {
            float a[4], b[4];
            #pragma unroll
            for (int i = 0; i < 4; i++) a[i] = As[k][ty * 4 + i];
            #pragma unroll
            for (int j = 0; j < 4; j++) b[j] = Bs[k][tx * 4 + j];
            #pragma unroll
            for (int i = 0; i < 4; i++)
                #pragma unroll
                for (int j = 0; j < 4; j++) acc[i][j] += a[i] * b[j];
        }
        __syncthreads();
    }
    #pragma unroll
    for (int i = 0; i < 4; i++) {
        int node = row0 + ty * 4 + i;
        if (node < N) {
            #pragma unroll
            for (int j = 0; j < 4; j++)
                g_h1[(size_t)node * HD1 + tx * 4 + j] = acc[i][j];
        }
    }
}

// ---------------- s1 --------------------------------------------------------
__global__ void s1_kernel(const float* __restrict__ a_src, const float* __restrict__ a_dst, int N) {
    int w = (blockIdx.x * blockDim.x + threadIdx.x) >> 5;
    int lane = threadIdx.x & 31;
    if (w >= N) return;
    const float* h = g_h1 + (size_t)w * HD1;
    float v0 = h[lane], v1 = h[lane + 32];
    float ss = v0 * a_src[lane] + v1 * a_src[lane + 32];
    float sd = v0 * a_dst[lane] + v1 * a_dst[lane + 32];
    #pragma unroll
    for (int o = 16; o; o >>= 1) {
        ss += __shfl_down_sync(0xFFFFFFFFu, ss, o);
        sd += __shfl_down_sync(0xFFFFFFFFu, sd, o);
    }
    if (lane == 0) { g_ssrc[w] = ss; g_sdst[w] = sd; }
}

// ---------------- layer-1 gather: warp per dst ------------------------------
// t1[d] = relu( (1/z) * sum_e p_e * h1[src_e] + b1 ),  p_e = exp(leaky(e))
__global__ void gather64(const float* __restrict__ b1, int N) {
    int gid = blockIdx.x * blockDim.x + threadIdx.x;
    int w = gid >> 5, lane = gid & 31;
    if (w >= N) return;
    int beg = g_rowptr[w], end = g_rowptr[w + 1];
    float sd = g_sdst[w];
    float2 acc = make_float2(0.f, 0.f);
    float z = 0.f;
    for (int i = beg; i < end; i++) {
        int s = __ldg(&g_esrc[i]);
        float e = __ldg(&g_ssrc[s]) + sd;
        e = e > 0.f ? e : 0.2f * e;
        float p = __expf(e);
        z += p;
        float2 hv = *(const float2*)(g_h1 + (size_t)s * HD1 + lane * 2);
        acc.x += p * hv.x;
        acc.y += p * hv.y;
    }
    float inv = __fdividef(1.f, z);
    float2 bb = *(const float2*)(b1 + lane * 2);
    float2 o;
    o.x = fmaxf(acc.x * inv + bb.x, 0.f);
    o.y = fmaxf(acc.y * inv + bb.y, 0.f);
    *(float2*)(g_t1 + (size_t)w * HD1 + lane * 2) = o;
}

// ---------------- GEMM2: h2 = t1 @ W2 ---------------------------------------
__global__ void gemm2_kernel(const float* __restrict__ W2, int N) {
    __shared__ float Os[128][65];
    __shared__ float Ws[64][17];
    int tid = threadIdx.x;                 // 128 threads
    int node0 = blockIdx.x * 128;
    for (int i = tid; i < HD1 * HD2; i += 128) Ws[i >> 4][i & 15] = W2[i];
    for (int i = tid; i < 128 * HD1; i += 128) {
        int r = i >> 6, k = i & 63;
        int node = node0 + r;
        Os[r][k] = (node < N) ? g_t1[(size_t)node * HD1 + k] : 0.f;
    }
    __syncthreads();
    int node = node0 + tid;
    if (node >= N) return;
    float acc[16] = {};
    #pragma unroll 4
    for (int k = 0; k < HD1; k++) {
        float v = Os[tid][k];
        #pragma unroll
        for (int j = 0; j < HD2; j++) acc[j] += v * Ws[k][j];
    }
    float4* out = (float4*)(g_h2 + (size_t)node * HD2);
    out[0] = make_float4(acc[0], acc[1], acc[2], acc[3]);
    out[1] = make_float4(acc[4], acc[5], acc[6], acc[7]);
    out[2] = make_float4(acc[8], acc[9], acc[10], acc[11]);
    out[3] = make_float4(acc[12], acc[13], acc[14], acc[15]);
}

// ---------------- s2 --------------------------------------------------------
__global__ void s2_kernel(const float* __restrict__ a_src, const float* __restrict__ a_dst, int N) {
    int n = blockIdx.x * blockDim.x + threadIdx.x;
    if (n >= N) return;
    const float* h = g_h2 + (size_t)n * HD2;
    float ss = 0.f, sd = 0.f;
    #pragma unroll
    for (int i = 0; i < HD2; i++) {
        float v = h[i];
        ss += v * __ldg(&a_src[i]);
        sd += v * __ldg(&a_dst[i]);
    }
    g_ssrc[n] = ss;
    g_sdst[n] = sd;
}

// ---------------- layer-2 gather: 8 lanes per dst ---------------------------
__global__ void gather16(int N) {
    int gid = blockIdx.x * blockDim.x + threadIdx.x;
    int d = gid >> 3, l = gid & 7;
    if (d >= N) return;
    int beg = g_rowptr[d], end = g_rowptr[d + 1];
    float sd = g_sdst[d];
    float2 acc = make_float2(0.f, 0.f);
    float z = 0.f;
    for (int i = beg; i < end; i++) {
        int s = __ldg(&g_esrc[i]);
        float e = __ldg(&g_ssrc[s]) + sd;
        e = e > 0.f ? e : 0.2f * e;
        float p = __expf(e);
        z += p;
        float2 hv = *(const float2*)(g_h2 + (size_t)s * HD2 + l * 2);
        acc.x += p * hv.x;
        acc.y += p * hv.y;
    }
    float inv = __fdividef(1.f, z);
    float2 o = make_float2(acc.x * inv, acc.y * inv);
    *(float2*)(g_o2 + (size_t)d * HD2 + l * 2) = o;
}

// ---------------- classifier + log_softmax ----------------------------------
__global__ void final_kernel(const float* __restrict__ b2, const float* __restrict__ Wc,
                             const float* __restrict__ bc, float* __restrict__ out, int N) {
    __shared__ float Wcs[HD2 * NCLS];
    __shared__ float bcs[NCLS];
    __shared__ float b2s[HD2];
    int tid = threadIdx.x;                 // 128 threads
    for (int i = tid; i < HD2 * NCLS; i += 128) Wcs[i] = Wc[i];
    if (tid < NCLS) bcs[tid] = bc[tid];
    if (tid < HD2) b2s[tid] = b2[tid];
    __syncthreads();
    int n = blockIdx.x * 128 + tid;
    if (n >= N) return;
    float h[HD2];
    const float4* hv = (const float4*)(g_o2 + (size_t)n * HD2);
    #pragma unroll
    for (int i = 0; i < 4; i++) {
        float4 v = hv[i];
        h[i * 4 + 0] = v.x + b2s[i * 4 + 0];
        h[i * 4 + 1] = v.y + b2s[i * 4 + 1];
        h[i * 4 + 2] = v.z + b2s[i * 4 + 2];
        h[i * 4 + 3] = v.w + b2s[i * 4 + 3];
    }
    float logits[NCLS];
    #pragma unroll
    for (int c = 0; c < NCLS; c++) {
        float acc = bcs[c];
        #pragma unroll
        for (int k = 0; k < HD2; k++) acc += h[k] * Wcs[k * NCLS + c];
        logits[c] = acc;
    }
    float mx = logits[0];
    #pragma unroll
    for (int c = 1; c < NCLS; c++) mx = fmaxf(mx, logits[c]);
    float sum = 0.f;
    #pragma unroll
    for (int c = 0; c < NCLS; c++) sum += __expf(logits[c] - mx);
    float lse = mx + logf(sum);
    #pragma unroll
    for (int c = 0; c < NCLS; c++) out[(size_t)n * NCLS + c] = logits[c] - lse;
}

// ---------------- launch -----------------------------------------------------
extern "C" void kernel_launch(void* const* d_in, const int* in_sizes, int n_in,
                              void* d_out, int out_size) {
    const float* x   = (const float*)d_in[0];
    const void*  ei  = d_in[1];
    const float* W1  = (const float*)d_in[2];
    const float* a1s = (const float*)d_in[3];
    const float* a1d = (const float*)d_in[4];
    const float* b1  = (const float*)d_in[5];
    const float* W2  = (const float*)d_in[6];
    const float* a2s = (const float*)d_in[7];
    const float* a2d = (const float*)d_in[8];
    const float* b2  = (const float*)d_in[9];
    const float* Wc  = (const float*)d_in[10];
    const float* bc  = (const float*)d_in[11];
    float* out = (float*)d_out;

    int N = in_sizes[0] / FIN;
    int E = in_sizes[1] / 2;
    int Etot = E + N;
    int NB = CDIV(N, 256);      // <= 512 for N <= 131072

    // edge prep + CSR sort (shared by both layers)
    detect_kernel<<<1, 32>>>(ei, E, N);
    zero_deg<<<CDIV(N, 256), 256>>>(N);
    convert_kernel<<<CDIV(Etot, 256), 256>>>(ei, E, N);
    scanA<<<NB, 256>>>(N);
    scanB<<<1, 512>>>(NB, N, Etot);
    scanC<<<NB, 256>>>(N);
    scatter_kernel<<<CDIV(Etot, 256), 256>>>(Etot);

    // layer 1
    gemm1_kernel<<<CDIV(N, 64), 256>>>(x, W1, N);
    s1_kernel<<<CDIV(N * 32, 256), 256>>>(a1s, a1d, N);
    gather64<<<CDIV(N * 32, 256), 256>>>(b1, N);

    // layer 2
    gemm2_kernel<<<CDIV(N, 128), 128>>>(W2, N);
    s2_kernel<<<CDIV(N, 256), 256>>>(a2s, a2d, N);
    gather16<<<CDIV(N * 8, 256), 256>>>(N);

    // classifier
    final_kernel<<<CDIV(N, 128), 128>>>(b2, Wc, bc, out, N);
}

// round 7
// speedup vs baseline: 2.1900x; 1.0657x over previous
#include <cuda_runtime.h>
#include <cuda_fp16.h>
#include <math.h>

#define MAXN 100000
#define MAXE 3200000
#define MAXET (MAXE + MAXN)
#define FIN 128
#define HD1 64
#define HD2 16
#define NCLS 10
#define CDIV(a,b) (((a)+(b)-1)/(b))

// ---------------- scratch ---------------------------------------------------
__device__ __align__(128) int    g_esrc[MAXET];     // CSR column (src) array
__device__ __align__(128) int    g_deg[MAXN];
__device__ __align__(128) int    g_rowptr[MAXN + 1];
__device__ __align__(128) int    g_cur[MAXN];
__device__ __align__(128) int    g_bsum[512];
__device__ __align__(128) __half g_h1h[(size_t)MAXN * HD1];   // fp16 h1
__device__ __align__(128) float  g_t1[(size_t)MAXN * HD1];    // relu(agg/z + b1)
__device__ __align__(128) __half g_h2h[(size_t)MAXN * HD2];   // fp16 h2
__device__ __align__(128) float  g_o2[(size_t)MAXN * HD2];
__device__ __align__(128) float  g_ssrc[MAXN];
__device__ __align__(128) float  g_sdst[MAXN];
__device__ int g_is64;

// ---------------- edge prep -------------------------------------------------
__global__ void detect_kernel(const void* ei, int E, int N) {
    if (blockIdx.x == 0 && threadIdx.x == 0) {
        const long long* p = (const long long*)ei;
        int n = 2 * E; if (n > 64) n = 64;
        int ok = 1;
        for (int i = 0; i < n; i++) {
            long long v = p[i];
            if (v < 0 || v >= (long long)N) { ok = 0; break; }
        }
        g_is64 = ok;
    }
}

__global__ void init_deg(int N) {     // start at 1: accounts for the self-loop
    int i = blockIdx.x * blockDim.x + threadIdx.x;
    if (i < N) g_deg[i] = 1;
}

// histogram over dst half of edge_index
__global__ void deg_kernel(const void* ei, int E) {
    int e = blockIdx.x * blockDim.x + threadIdx.x;
    if (e >= E) return;
    int d;
    if (g_is64) d = (int)((const long long*)ei)[(size_t)E + e];
    else        d = ((const int*)ei)[E + e];
    atomicAdd(&g_deg[d], 1);
}

// ---------------- prefix sum (3-phase block scan) ---------------------------
__global__ void scanA(int N) {
    __shared__ int sm[256];
    int tid = threadIdx.x;
    int i = blockIdx.x * 256 + tid;
    int v = (i < N) ? g_deg[i] : 0;
    sm[tid] = v;
    __syncthreads();
    #pragma unroll
    for (int o = 1; o < 256; o <<= 1) {
        int t = (tid >= o) ? sm[tid - o] : 0;
        __syncthreads();
        sm[tid] += t;
        __syncthreads();
    }
    if (i < N) g_rowptr[i] = sm[tid] - v;
    if (tid == 255) g_bsum[blockIdx.x] = sm[255];
}

__global__ void scanB(int nb, int N, int Etot) {
    __shared__ int sm[512];
    int tid = threadIdx.x;
    int v = (tid < nb) ? g_bsum[tid] : 0;
    sm[tid] = v;
    __syncthreads();
    #pragma unroll
    for (int o = 1; o < 512; o <<= 1) {
        int t = (tid >= o) ? sm[tid - o] : 0;
        __syncthreads();
        sm[tid] += t;
        __syncthreads();
    }
    if (tid < nb) g_bsum[tid] = sm[tid] - v;
    if (tid == 0) g_rowptr[N] = Etot;
}

__global__ void scanC(int N) {
    int i = blockIdx.x * 256 + threadIdx.x;
    if (i < N) {
        int v = g_rowptr[i] + g_bsum[blockIdx.x];
        g_rowptr[i] = v;
        g_cur[i] = v;
    }
}

// place edges (reads edge_index directly) + self-loops
__global__ void scatter_kernel(const void* ei, int E, int N) {
    int e = blockIdx.x * blockDim.x + threadIdx.x;
    int tot = E + N;
    if (e >= tot) return;
    int s, d;
    if (e < E) {
        if (g_is64) {
            const long long* p = (const long long*)ei;
            s = (int)p[e];
            d = (int)p[(size_t)E + e];
        } else {
            const int* p = (const int*)ei;
            s = p[e];
            d = p[E + e];
        }
    } else {
        s = e - E; d = e - E;
    }
    int pos = atomicAdd(&g_cur[d], 1);
    g_esrc[pos] = s;
}

// ---------------- GEMM1: h1 = x @ W1 (+ fused s1, fp16 h1 out) ---------------
__global__ void gemm1_kernel(const float* __restrict__ x, const float* __restrict__ W,
                             const float* __restrict__ a_src, const float* __restrict__ a_dst,
                             int N) {
    __shared__ float As[32][68];
    __shared__ float Bs[32][68];
    int tid = threadIdx.x;                 // 256 threads
    int ty = tid >> 4, tx = tid & 15;
    int row0 = blockIdx.x * 64;
    float acc[4][4] = {};
    for (int kt = 0; kt < FIN; kt += 32) {
        #pragma unroll
        for (int i = 0; i < 8; i++) {
            int l = tid + i * 256;
            int k = l & 31, r = l >> 5;
            int node = row0 + r;
            As[k][r] = (node < N) ? x[(size_t)node * FIN + kt + k] : 0.f;
        }
        #pragma unroll
        for (int i = 0; i < 8; i++) {
            int l = tid + i * 256;
            int col = l & 63, k = l >> 6;
            Bs[k][col] = W[(kt + k) * HD1 + col];
        }
        __syncthreads();
        #pragma unroll
        for (int k = 0; k < 32; k++) {
            float a[4], b[4];
            #pragma unroll
            for (int i = 0; i < 4; i++) a[i] = As[k][ty * 4 + i];
            #pragma unroll
            for (int j = 0; j < 4; j++) b[j] = Bs[k][tx * 4 + j];
            #pragma unroll
            for (int i = 0; i < 4; i++)
                #pragma unroll
                for (int j = 0; j < 4; j++) acc[i][j] += a[i] * b[j];
        }
        __syncthreads();
    }
    // fp16 h1 store
    #pragma unroll
    for (int i = 0; i < 4; i++) {
        int node = row0 + ty * 4 + i;
        if (node < N) {
            __half2* hp = (__half2*)(g_h1h + (size_t)node * HD1 + tx * 4);
            hp[0] = __floats2half2_rn(acc[i][0], acc[i][1]);
            hp[1] = __floats2half2_rn(acc[i][2], acc[i][3]);
        }
    }
    // fused s1: reduce acc rows against a_src/a_dst across the 16 tx lanes
    float as[4], ad[4];
    #pragma unroll
    for (int j = 0; j < 4; j++) { as[j] = __ldg(&a_src[tx * 4 + j]); ad[j] = __ldg(&a_dst[tx * 4 + j]); }
    #pragma unroll
    for (int i = 0; i < 4; i++) {
        float ss = acc[i][0]*as[0] + acc[i][1]*as[1] + acc[i][2]*as[2] + acc[i][3]*as[3];
        float sd = acc[i][0]*ad[0] + acc[i][1]*ad[1] + acc[i][2]*ad[2] + acc[i][3]*ad[3];
        #pragma unroll
        for (int o = 8; o; o >>= 1) {
            ss += __shfl_down_sync(0xFFFFFFFFu, ss, o);
            sd += __shfl_down_sync(0xFFFFFFFFu, sd, o);
        }
        if (tx == 0) {
            int node = row0 + ty * 4 + i;
            if (node < N) { g_ssrc[node] = ss; g_sdst[node] = sd; }
        }
    }
}

// ---------------- layer-1 gather: warp per dst, chunked shfl -----------------
__global__ void gather64(const float* __restrict__ b1, int N) {
    int gid = blockIdx.x * blockDim.x + threadIdx.x;
    int w = gid >> 5, lane = gid & 31;
    if (w >= N) return;
    int beg = g_rowptr[w], end = g_rowptr[w + 1];
    float sd = g_sdst[w];
    float2 acc = make_float2(0.f, 0.f);
    float z = 0.f;
    const __half2* h1v = (const __half2*)g_h1h;
    for (int base = beg; base < end; base += 32) {
        int i = base + lane;
        int my_s = 0; float my_p = 0.f;
        if (i < end) {
            my_s = __ldg(&g_esrc[i]);
            float e = __ldg(&g_ssrc[my_s]) + sd;
            e = e > 0.f ? e : 0.2f * e;
            my_p = __expf(e);
        }
        int cnt = min(32, end - base);
        for (int j = 0; j < cnt; j++) {
            int   s = __shfl_sync(0xFFFFFFFFu, my_s, j);
            float p = __shfl_sync(0xFFFFFFFFu, my_p, j);
            z += p;
            float2 hv = __half22float2(h1v[s * 32 + lane]);
            acc.x += p * hv.x;
            acc.y += p * hv.y;
        }
    }
    float inv = __fdividef(1.f, z);
    float2 bb = *(const float2*)(b1 + lane * 2);
    float2 o;
    o.x = fmaxf(acc.x * inv + bb.x, 0.f);
    o.y = fmaxf(acc.y * inv + bb.y, 0.f);
    *(float2*)(g_t1 + (size_t)w * HD1 + lane * 2) = o;
}

// ---------------- GEMM2: h2 = t1 @ W2 (+ fused s2, fp16 h2 out) --------------
__global__ void gemm2_kernel(const float* __restrict__ W2,
                             const float* __restrict__ a_src, const float* __restrict__ a_dst,
                             int N) {
    __shared__ float Os[128][65];
    __shared__ float Ws[64][17];
    int tid = threadIdx.x;                 // 128 threads
    int node0 = blockIdx.x * 128;
    for (int i = tid; i < HD1 * HD2; i += 128) Ws[i >> 4][i & 15] = W2[i];
    for (int i = tid; i < 128 * HD1; i += 128) {
        int r = i >> 6, k = i & 63;
        int node = node0 + r;
        Os[r][k] = (node < N) ? g_t1[(size_t)node * HD1 + k] : 0.f;
    }
    __syncthreads();
    int node = node0 + tid;
    if (node >= N) return;
    float acc[16] = {};
    #pragma unroll 4
    for (int k = 0; k < HD1; k++) {
        float v = Os[tid][k];
        #pragma unroll
        for (int j = 0; j < HD2; j++) acc[j] += v * Ws[k][j];
    }
    __half2* hp = (__half2*)(g_h2h + (size_t)node * HD2);
    #pragma unroll
    for (int j = 0; j < 8; j++) hp[j] = __floats2half2_rn(acc[2*j], acc[2*j+1]);
    float ss = 0.f, sdv = 0.f;
    #pragma unroll
    for (int j = 0; j < HD2; j++) {
        ss  += acc[j] * __ldg(&a_src[j]);
        sdv += acc[j] * __ldg(&a_dst[j]);
    }
    g_ssrc[node] = ss;
    g_sdst[node] = sdv;
}

// ---------------- layer-2 gather: 8 lanes per dst, chunked shfl --------------
__global__ void gather16(int N) {
    int gid = blockIdx.x * blockDim.x + threadIdx.x;
    int d = gid >> 3, l = gid & 7;
    if (d >= N) return;
    int beg = g_rowptr[d], end = g_rowptr[d + 1];
    float sd = g_sdst[d];
    float2 acc = make_float2(0.f, 0.f);
    float z = 0.f;
    const __half2* h2v = (const __half2*)g_h2h;
    for (int base = beg; base < end; base += 8) {
        int i = base + l;
        int my_s = 0; float my_p = 0.f;
        if (i < end) {
            my_s = __ldg(&g_esrc[i]);
            float e = __ldg(&g_ssrc[my_s]) + sd;
            e = e > 0.f ? e : 0.2f * e;
            my_p = __expf(e);
        }
        int cnt = min(8, end - base);
        for (int j = 0; j < cnt; j++) {
            int   s = __shfl_sync(0xFFFFFFFFu, my_s, j, 8);
            float p = __shfl_sync(0xFFFFFFFFu, my_p, j, 8);
            z += p;
            float2 hv = __half22float2(h2v[s * 8 + l]);
            acc.x += p * hv.x;
            acc.y += p * hv.y;
        }
    }
    float inv = __fdividef(1.f, z);
    *(float2*)(g_o2 + (size_t)d * HD2 + l * 2) = make_float2(acc.x * inv, acc.y * inv);
}

// ---------------- classifier + log_softmax ----------------------------------
__global__ void final_kernel(const float* __restrict__ b2, const float* __restrict__ Wc,
                             const float* __restrict__ bc, float* __restrict__ out, int N) {
    __shared__ float Wcs[HD2 * NCLS];
    __shared__ float bcs[NCLS];
    __shared__ float b2s[HD2];
    int tid = threadIdx.x;                 // 128 threads
    for (int i = tid; i < HD2 * NCLS; i += 128) Wcs[i] = Wc[i];
    if (tid < NCLS) bcs[tid] = bc[tid];
    if (tid < HD2) b2s[tid] = b2[tid];
    __syncthreads();
    int n = blockIdx.x * 128 + tid;
    if (n >= N) return;
    float h[HD2];
    const float4* hv = (const float4*)(g_o2 + (size_t)n * HD2);
    #pragma unroll
    for (int i = 0; i < 4; i++) {
        float4 v = hv[i];
        h[i * 4 + 0] = v.x + b2s[i * 4 + 0];
        h[i * 4 + 1] = v.y + b2s[i * 4 + 1];
        h[i * 4 + 2] = v.z + b2s[i * 4 + 2];
        h[i * 4 + 3] = v.w + b2s[i * 4 + 3];
    }
    float logits[NCLS];
    #pragma unroll
    for (int c = 0; c < NCLS; c++) {
        float acc = bcs[c];
        #pragma unroll
        for (int k = 0; k < HD2; k++) acc += h[k] * Wcs[k * NCLS + c];
        logits[c] = acc;
    }
    float mx = logits[0];
    #pragma unroll
    for (int c = 1; c < NCLS; c++) mx = fmaxf(mx, logits[c]);
    float sum = 0.f;
    #pragma unroll
    for (int c = 0; c < NCLS; c++) sum += __expf(logits[c] - mx);
    float lse = mx + logf(sum);
    #pragma unroll
    for (int c = 0; c < NCLS; c++) out[(size_t)n * NCLS + c] = logits[c] - lse;
}

// ---------------- launch -----------------------------------------------------
extern "C" void kernel_launch(void* const* d_in, const int* in_sizes, int n_in,
                              void* d_out, int out_size) {
    const float* x   = (const float*)d_in[0];
    const void*  ei  = d_in[1];
    const float* W1  = (const float*)d_in[2];
    const float* a1s = (const float*)d_in[3];
    const float* a1d = (const float*)d_in[4];
    const float* b1  = (const float*)d_in[5];
    const float* W2  = (const float*)d_in[6];
    const float* a2s = (const float*)d_in[7];
    const float* a2d = (const float*)d_in[8];
    const float* b2  = (const float*)d_in[9];
    const float* Wc  = (const float*)d_in[10];
    const float* bc  = (const float*)d_in[11];
    float* out = (float*)d_out;

    int N = in_sizes[0] / FIN;
    int E = in_sizes[1] / 2;
    int Etot = E + N;
    int NB = CDIV(N, 256);

    // edge prep + CSR (shared by both layers)
    detect_kernel<<<1, 32>>>(ei, E, N);
    init_deg<<<CDIV(N, 256), 256>>>(N);
    deg_kernel<<<CDIV(E, 256), 256>>>(ei, E);
    scanA<<<NB, 256>>>(N);
    scanB<<<1, 512>>>(NB, N, Etot);
    scanC<<<NB, 256>>>(N);
    scatter_kernel<<<CDIV(Etot, 256), 256>>>(ei, E, N);

    // layer 1
    gemm1_kernel<<<CDIV(N, 64), 256>>>(x, W1, a1s, a1d, N);
    gather64<<<CDIV(N * 32, 256), 256>>>(b1, N);

    // layer 2
    gemm2_kernel<<<CDIV(N, 128), 128>>>(W2, a2s, a2d, N);
    gather16<<<CDIV(N * 8, 256), 256>>>(N);

    // classifier
    final_kernel<<<CDIV(N, 128), 128>>>(b2, Wc, bc, out, N);
}

// round 10
// speedup vs baseline: 2.3180x; 1.0584x over previous
#include <cuda_runtime.h>
#include <cuda_fp16.h>
#include <cstdint>
#include <math.h>

#define MAXN 100000
#define MAXE 3200000
#define MAXET (MAXE + MAXN)
#define FIN 128
#define HD1 64
#define HD2 16
#define NCLS 10
#define CDIV(a,b) (((a)+(b)-1)/(b))

// ---------------- scratch ---------------------------------------------------
__device__ __align__(128) int    g_esrc[MAXET];
__device__ __align__(128) int    g_deg[MAXN];
__device__ __align__(128) int    g_rowptr[MAXN + 1];
__device__ __align__(128) int    g_cur[MAXN];
__device__ __align__(128) int    g_bsum[512];
__device__ __align__(128) __half g_h1h[(size_t)MAXN * HD1];
__device__ __align__(128) float  g_t1[(size_t)MAXN * HD1];
__device__ __align__(128) __half g_h2h[(size_t)MAXN * HD2];
__device__ __align__(128) float  g_o2[(size_t)MAXN * HD2];
__device__ __align__(128) float  g_ssrc[MAXN];
__device__ __align__(128) float  g_sdst[MAXN];
__device__ __align__(128) float  g_ws[FIN];   // W1 @ a1_src
__device__ __align__(128) float  g_wd[FIN];   // W1 @ a1_dst
__device__ int g_is64;

// ---------------- mma helpers ------------------------------------------------
__device__ __forceinline__ uint32_t cvt_tf32(float f) {
    uint32_t r; asm("cvt.rna.tf32.f32 %0, %1;" : "=r"(r) : "f"(f)); return r;
}
__device__ __forceinline__ void mma_tf32(float* d, uint32_t a0, uint32_t a1,
                                         uint32_t a2, uint32_t a3,
                                         uint32_t b0, uint32_t b1) {
    asm volatile("mma.sync.aligned.m16n8k8.row.col.f32.tf32.tf32.f32 "
        "{%0,%1,%2,%3}, {%4,%5,%6,%7}, {%8,%9}, {%0,%1,%2,%3};"
        : "+f"(d[0]), "+f"(d[1]), "+f"(d[2]), "+f"(d[3])
        : "r"(a0), "r"(a1), "r"(a2), "r"(a3), "r"(b0), "r"(b1));
}

// ---------------- edge prep + w-vectors --------------------------------------
__global__ void detect_kernel(const void* ei, const float* __restrict__ W,
                              const float* __restrict__ a1s, const float* __restrict__ a1d,
                              int E, int N) {
    int tid = threadIdx.x;          // 128 threads
    if (tid == 0) {
        const long long* p = (const long long*)ei;
        int n = 2 * E; if (n > 64) n = 64;
        int ok = 1;
        for (int i = 0; i < n; i++) {
            long long v = p[i];
            if (v < 0 || v >= (long long)N) { ok = 0; break; }
        }
        g_is64 = ok;
    }
    if (tid < FIN) {                // w_s/w_d = W1 @ a  (exact fp32 s-path)
        float ss = 0.f, sd = 0.f;
        for (int j = 0; j < HD1; j++) {
            float w = W[tid * HD1 + j];
            ss += w * a1s[j];
            sd += w * a1d[j];
        }
        g_ws[tid] = ss;
        g_wd[tid] = sd;
    }
}

__global__ void init_deg(int N) {   // =1 accounts for the self-loop
    int i = blockIdx.x * blockDim.x + threadIdx.x;
    if (i < N) g_deg[i] = 1;
}

__global__ void deg_kernel(const void* ei, int E) {
    int e = blockIdx.x * blockDim.x + threadIdx.x;
    if (e >= E) return;
    int d;
    if (g_is64) d = (int)((const long long*)ei)[(size_t)E + e];
    else        d = ((const int*)ei)[E + e];
    atomicAdd(&g_deg[d], 1);
}

// ---------------- prefix sum ------------------------------------------------
__global__ void scanA(int N) {
    __shared__ int sm[256];
    int tid = threadIdx.x;
    int i = blockIdx.x * 256 + tid;
    int v = (i < N) ? g_deg[i] : 0;
    sm[tid] = v;
    __syncthreads();
    #pragma unroll
    for (int o = 1; o < 256; o <<= 1) {
        int t = (tid >= o) ? sm[tid - o] : 0;
        __syncthreads();
        sm[tid] += t;
        __syncthreads();
    }
    if (i < N) g_rowptr[i] = sm[tid] - v;
    if (tid == 255) g_bsum[blockIdx.x] = sm[255];
}

__global__ void scanB(int nb, int N, int Etot) {
    __shared__ int sm[512];
    int tid = threadIdx.x;
    int v = (tid < nb) ? g_bsum[tid] : 0;
    sm[tid] = v;
    __syncthreads();
    #pragma unroll
    for (int o = 1; o < 512; o <<= 1) {
        int t = (tid >= o) ? sm[tid - o] : 0;
        __syncthreads();
        sm[tid] += t;
        __syncthreads();
    }
    if (tid < nb) g_bsum[tid] = sm[tid] - v;
    if (tid == 0) g_rowptr[N] = Etot;
}

__global__ void scanC(int N) {
    int i = blockIdx.x * 256 + threadIdx.x;
    if (i < N) {
        int v = g_rowptr[i] + g_bsum[blockIdx.x];
        g_rowptr[i] = v;
        g_cur[i] = v;
    }
}

__global__ void scatter_kernel(const void* ei, int E, int N) {
    int e = blockIdx.x * blockDim.x + threadIdx.x;
    int tot = E + N;
    if (e >= tot) return;
    int s, d;
    if (e < E) {
        if (g_is64) {
            const long long* p = (const long long*)ei;
            s = (int)p[e];
            d = (int)p[(size_t)E + e];
        } else {
            const int* p = (const int*)ei;
            s = p[e];
            d = p[E + e];
        }
    } else {
        s = e - E; d = e - E;
    }
    int pos = atomicAdd(&g_cur[d], 1);
    g_esrc[pos] = s;
}

// ---------------- GEMM1 (tf32 HMMA): h1 = x@W1, fp16 out, exact fp32 s1 ------
// 256 threads = 8 warps; block tile 128 rows x 64 cols; warp tile 16x64.
// Smem row strides are multiples of 4 floats so float4 staging stays aligned.
__global__ void gemm1_tc(const float* __restrict__ x, const float* __restrict__ W, int N) {
    __shared__ float As[128][36];   // 144 B/row: 16B-aligned, +4 bank skew
    __shared__ float Bs[32][68];    // 272 B/row: 16B-aligned, +4 bank skew
    __shared__ float ws[FIN], wd[FIN];
    int tid = threadIdx.x;
    int warp = tid >> 5, lane = tid & 31;
    int row0 = blockIdx.x * 128;
    if (tid < FIN) { ws[tid] = g_ws[tid]; wd[tid] = g_wd[tid]; }

    float d[8][4] = {};
    float ssacc = 0.f, sdacc = 0.f;
    int sr = lane >> 1, sh = lane & 1;       // s-compute: 2 lanes per row

    for (int kt = 0; kt < FIN; kt += 32) {
        __syncthreads();                     // protect As/ws before (re)use
        #pragma unroll
        for (int i = 0; i < 4; i++) {        // stage A: 128 x 32
            int l = tid + i * 256;
            int rr = l >> 3, c4 = (l & 7) * 4;
            int node = row0 + rr;
            float4 v = make_float4(0.f, 0.f, 0.f, 0.f);
            if (node < N) v = *(const float4*)(x + (size_t)node * FIN + kt + c4);
            *(float4*)&As[rr][c4] = v;
        }
        #pragma unroll
        for (int i = 0; i < 2; i++) {        // stage B: 32 x 64
            int l = tid + i * 256;
            int kk = l >> 4, c4 = (l & 15) * 4;
            *(float4*)&Bs[kk][c4] = *(const float4*)(W + (size_t)(kt + kk) * HD1 + c4);
        }
        __syncthreads();

        #pragma unroll
        for (int ks = 0; ks < 4; ks++) {
            int k0 = ks * 8;
            int ar = warp * 16 + (lane >> 2);
            int ac = k0 + (lane & 3);
            uint32_t a0 = cvt_tf32(As[ar][ac]);
            uint32_t a1 = cvt_tf32(As[ar + 8][ac]);
            uint32_t a2 = cvt_tf32(As[ar][ac + 4]);
            uint32_t a3 = cvt_tf32(As[ar + 8][ac + 4]);
            #pragma unroll
            for (int nt = 0; nt < 8; nt++) {
                int bc = nt * 8 + (lane >> 2);
                uint32_t b0 = cvt_tf32(Bs[k0 + (lane & 3)][bc]);
                uint32_t b1 = cvt_tf32(Bs[k0 + (lane & 3) + 4][bc]);
                mma_tf32(d[nt], a0, a1, a2, a3, b0, b1);
            }
        }
        // exact fp32 s: s[row] += x[row, kt..kt+32) . ws/wd
        {
            const float* arow = As[warp * 16 + sr];
            #pragma unroll
            for (int k = 0; k < 16; k++) {
                float v = arow[sh * 16 + k];
                ssacc += v * ws[kt + sh * 16 + k];
                sdacc += v * wd[kt + sh * 16 + k];
            }
        }
    }

    // store h1 as fp16 (D frag: d0,d1 adjacent cols, rows g / g+8)
    int orow0 = row0 + warp * 16 + (lane >> 2);
    int orow1 = orow0 + 8;
    #pragma unroll
    for (int nt = 0; nt < 8; nt++) {
        int col = nt * 8 + (lane & 3) * 2;
        if (orow0 < N)
            *(__half2*)(g_h1h + (size_t)orow0 * HD1 + col) = __floats2half2_rn(d[nt][0], d[nt][1]);
        if (orow1 < N)
            *(__half2*)(g_h1h + (size_t)orow1 * HD1 + col) = __floats2half2_rn(d[nt][2], d[nt][3]);
    }
    // s reduce (2 lanes/row) + store
    ssacc += __shfl_down_sync(0xFFFFFFFFu, ssacc, 1);
    sdacc += __shfl_down_sync(0xFFFFFFFFu, sdacc, 1);
    if (sh == 0) {
        int node = row0 + warp * 16 + sr;
        if (node < N) { g_ssrc[node] = ssacc; g_sdst[node] = sdacc; }
    }
}

// ---------------- layer-1 gather: warp per dst, chunked shfl -----------------
__global__ void gather64(const float* __restrict__ b1, int N) {
    int gid = blockIdx.x * blockDim.x + threadIdx.x;
    int w = gid >> 5, lane = gid & 31;
    if (w >= N) return;
    int beg = g_rowptr[w], end = g_rowptr[w + 1];
    float sd = g_sdst[w];
    float2 acc = make_float2(0.f, 0.f);
    float z = 0.f;
    const __half2* h1v = (const __half2*)g_h1h;
    for (int base = beg; base < end; base += 32) {
        int i = base + lane;
        int my_s = 0; float my_p = 0.f;
        if (i < end) {
            my_s = __ldg(&g_esrc[i]);
            float e = __ldg(&g_ssrc[my_s]) + sd;
            e = e > 0.f ? e : 0.2f * e;
            my_p = __expf(e);
        }
        int cnt = min(32, end - base);
        for (int j = 0; j < cnt; j++) {
            int   s = __shfl_sync(0xFFFFFFFFu, my_s, j);
            float p = __shfl_sync(0xFFFFFFFFu, my_p, j);
            z += p;
            float2 hv = __half22float2(h1v[s * 32 + lane]);
            acc.x += p * hv.x;
            acc.y += p * hv.y;
        }
    }
    float inv = __fdividef(1.f, z);
    float2 bb = *(const float2*)(b1 + lane * 2);
    float2 o;
    o.x = fmaxf(acc.x * inv + bb.x, 0.f);
    o.y = fmaxf(acc.y * inv + bb.y, 0.f);
    *(float2*)(g_t1 + (size_t)w * HD1 + lane * 2) = o;
}

// ---------------- GEMM2: h2 = t1 @ W2 (+ fused s2, fp16 h2 out) --------------
__global__ void gemm2_kernel(const float* __restrict__ W2,
                             const float* __restrict__ a_src, const float* __restrict__ a_dst,
                             int N) {
    __shared__ float Os[128][65];
    __shared__ float Ws[64][17];
    int tid = threadIdx.x;                 // 128 threads
    int node0 = blockIdx.x * 128;
    for (int i = tid; i < HD1 * HD2; i += 128) Ws[i >> 4][i & 15] = W2[i];
    for (int i = tid; i < 128 * HD1; i += 128) {
        int r = i >> 6, k = i & 63;
        int node = node0 + r;
        Os[r][k] = (node < N) ? g_t1[(size_t)node * HD1 + k] : 0.f;
    }
    __syncthreads();
    int node = node0 + tid;
    if (node >= N) return;
    float acc[16] = {};
    #pragma unroll 4
    for (int k = 0; k < HD1; k++) {
        float v = Os[tid][k];
        #pragma unroll
        for (int j = 0; j < HD2; j++) acc[j] += v * Ws[k][j];
    }
    __half2* hp = (__half2*)(g_h2h + (size_t)node * HD2);
    #pragma unroll
    for (int j = 0; j < 8; j++) hp[j] = __floats2half2_rn(acc[2*j], acc[2*j+1]);
    float ss = 0.f, sdv = 0.f;
    #pragma unroll
    for (int j = 0; j < HD2; j++) {
        ss  += acc[j] * __ldg(&a_src[j]);
        sdv += acc[j] * __ldg(&a_dst[j]);
    }
    g_ssrc[node] = ss;
    g_sdst[node] = sdv;
}

// ---------------- layer-2 gather: 8 lanes per dst, chunked shfl --------------
__global__ void gather16(int N) {
    int gid = blockIdx.x * blockDim.x + threadIdx.x;
    int d = gid >> 3, l = gid & 7;
    if (d >= N) return;
    int beg = g_rowptr[d], end = g_rowptr[d + 1];
    float sd = g_sdst[d];
    float2 acc = make_float2(0.f, 0.f);
    float z = 0.f;
    const __half2* h2v = (const __half2*)g_h2h;
    for (int base = beg; base < end; base += 8) {
        int i = base + l;
        int my_s = 0; float my_p = 0.f;
        if (i < end) {
            my_s = __ldg(&g_esrc[i]);
            float e = __ldg(&g_ssrc[my_s]) + sd;
            e = e > 0.f ? e : 0.2f * e;
            my_p = __expf(e);
        }
        int cnt = min(8, end - base);
        for (int j = 0; j < cnt; j++) {
            int   s = __shfl_sync(0xFFFFFFFFu, my_s, j, 8);
            float p = __shfl_sync(0xFFFFFFFFu, my_p, j, 8);
            z += p;
            float2 hv = __half22float2(h2v[s * 8 + l]);
            acc.x += p * hv.x;
            acc.y += p * hv.y;
        }
    }
    float inv = __fdividef(1.f, z);
    *(float2*)(g_o2 + (size_t)d * HD2 + l * 2) = make_float2(acc.x * inv, acc.y * inv);
}

// ---------------- classifier + log_softmax ----------------------------------
__global__ void final_kernel(const float* __restrict__ b2, const float* __restrict__ Wc,
                             const float* __restrict__ bc, float* __restrict__ out, int N) {
    __shared__ float Wcs[HD2 * NCLS];
    __shared__ float bcs[NCLS];
    __shared__ float b2s[HD2];
    int tid = threadIdx.x;                 // 128 threads
    for (int i = tid; i < HD2 * NCLS; i += 128) Wcs[i] = Wc[i];
    if (tid < NCLS) bcs[tid] = bc[tid];
    if (tid < HD2) b2s[tid] = b2[tid];
    __syncthreads();
    int n = blockIdx.x * 128 + tid;
    if (n >= N) return;
    float h[HD2];
    const float4* hv = (const float4*)(g_o2 + (size_t)n * HD2);
    #pragma unroll
    for (int i = 0; i < 4; i++) {
        float4 v = hv[i];
        h[i * 4 + 0] = v.x + b2s[i * 4 + 0];
        h[i * 4 + 1] = v.y + b2s[i * 4 + 1];
        h[i * 4 + 2] = v.z + b2s[i * 4 + 2];
        h[i * 4 + 3] = v.w + b2s[i * 4 + 3];
    }
    float logits[NCLS];
    #pragma unroll
    for (int c = 0; c < NCLS; c++) {
        float acc = bcs[c];
        #pragma unroll
        for (int k = 0; k < HD2; k++) acc += h[k] * Wcs[k * NCLS + c];
        logits[c] = acc;
    }
    float mx = logits[0];
    #pragma unroll
    for (int c = 1; c < NCLS; c++) mx = fmaxf(mx, logits[c]);
    float sum = 0.f;
    #pragma unroll
    for (int c = 0; c < NCLS; c++) sum += __expf(logits[c] - mx);
    float lse = mx + logf(sum);
    #pragma unroll
    for (int c = 0; c < NCLS; c++) out[(size_t)n * NCLS + c] = logits[c] - lse;
}

// ---------------- launch -----------------------------------------------------
extern "C" void kernel_launch(void* const* d_in, const int* in_sizes, int n_in,
                              void* d_out, int out_size) {
    const float* x   = (const float*)d_in[0];
    const void*  ei  = d_in[1];
    const float* W1  = (const float*)d_in[2];
    const float* a1s = (const float*)d_in[3];
    const float* a1d = (const float*)d_in[4];
    const float* b1  = (const float*)d_in[5];
    const float* W2  = (const float*)d_in[6];
    const float* a2s = (const float*)d_in[7];
    const float* a2d = (const float*)d_in[8];
    const float* b2  = (const float*)d_in[9];
    const float* Wc  = (const float*)d_in[10];
    const float* bc  = (const float*)d_in[11];
    float* out = (float*)d_out;

    int N = in_sizes[0] / FIN;
    int E = in_sizes[1] / 2;
    int Etot = E + N;
    int NB = CDIV(N, 256);

    // edge prep + CSR (shared by both layers) + w-vectors
    detect_kernel<<<1, 128>>>(ei, W1, a1s, a1d, E, N);
    init_deg<<<CDIV(N, 256), 256>>>(N);
    deg_kernel<<<CDIV(E, 256), 256>>>(ei, E);
    scanA<<<NB, 256>>>(N);
    scanB<<<1, 512>>>(NB, N, Etot);
    scanC<<<NB, 256>>>(N);
    scatter_kernel<<<CDIV(Etot, 256), 256>>>(ei, E, N);

    // layer 1
    gemm1_tc<<<CDIV(N, 128), 256>>>(x, W1, N);
    gather64<<<CDIV(N * 32, 256), 256>>>(b1, N);

    // layer 2
    gemm2_kernel<<<CDIV(N, 128), 128>>>(W2, a2s, a2d, N);
    gather16<<<CDIV(N * 8, 256), 256>>>(N);

    // classifier
    final_kernel<<<CDIV(N, 128), 128>>>(b2, Wc, bc, out, N);
}

// round 12
// speedup vs baseline: 2.3440x; 1.0112x over previous
#include <cuda_runtime.h>
#include <cuda_fp16.h>
#include <cstdint>
#include <math.h>

#define MAXN 100000
#define MAXE 3200000
#define MAXET (MAXE + MAXN)
#define FIN 128
#define HD1 64
#define HD2 16
#define NCLS 10
#define CDIV(a,b) (((a)+(b)-1)/(b))

// ---------------- scratch ---------------------------------------------------
__device__ __align__(128) int    g_esrc[MAXET];
__device__ __align__(128) int    g_deg[MAXN];
__device__ __align__(128) int    g_rowptr[MAXN + 1];
__device__ __align__(128) int    g_cur[MAXN];
__device__ __align__(128) int    g_bsum[512];
__device__ __align__(128) __half g_h1h[(size_t)MAXN * HD1];
__device__ __align__(128) float  g_t1[(size_t)MAXN * HD1];
__device__ __align__(128) __half g_h2h[(size_t)MAXN * HD2];
__device__ __align__(128) float  g_ssrc[MAXN];
__device__ __align__(128) float  g_sdst[MAXN];
__device__ __align__(128) float  g_ws[FIN];   // W1 @ a1_src
__device__ __align__(128) float  g_wd[FIN];   // W1 @ a1_dst
__device__ int g_is64;

// ---------------- mma helpers ------------------------------------------------
__device__ __forceinline__ uint32_t cvt_tf32(float f) {
    uint32_t r; asm("cvt.rna.tf32.f32 %0, %1;" : "=r"(r) : "f"(f)); return r;
}
__device__ __forceinline__ void mma_tf32(float* d, uint32_t a0, uint32_t a1,
                                         uint32_t a2, uint32_t a3,
                                         uint32_t b0, uint32_t b1) {
    asm volatile("mma.sync.aligned.m16n8k8.row.col.f32.tf32.tf32.f32 "
        "{%0,%1,%2,%3}, {%4,%5,%6,%7}, {%8,%9}, {%0,%1,%2,%3};"
        : "+f"(d[0]), "+f"(d[1]), "+f"(d[2]), "+f"(d[3])
        : "r"(a0), "r"(a1), "r"(a2), "r"(a3), "r"(b0), "r"(b1));
}

// ---------------- prep: dtype detect + w-vectors + deg init ------------------
__global__ void prep_kernel(const void* ei, const float* __restrict__ W,
                            const float* __restrict__ a1s, const float* __restrict__ a1d,
                            int E, int N) {
    int i = blockIdx.x * blockDim.x + threadIdx.x;
    if (i < N) g_deg[i] = 1;            // self-loop
    if (i == 0) {
        const long long* p = (const long long*)ei;
        int n = 2 * E; if (n > 64) n = 64;
        int ok = 1;
        for (int k = 0; k < n; k++) {
            long long v = p[k];
            if (v < 0 || v >= (long long)N) { ok = 0; break; }
        }
        g_is64 = ok;
    }
    if (i < FIN) {                      // exact fp32 s-path weights
        float ss = 0.f, sd = 0.f;
        for (int j = 0; j < HD1; j++) {
            float w = W[i * HD1 + j];
            ss += w * a1s[j];
            sd += w * a1d[j];
        }
        g_ws[i] = ss;
        g_wd[i] = sd;
    }
}

__global__ void deg_kernel(const void* ei, int E) {
    int e = blockIdx.x * blockDim.x + threadIdx.x;
    if (e >= E) return;
    int d;
    if (g_is64) d = (int)((const long long*)ei)[(size_t)E + e];
    else        d = ((const int*)ei)[E + e];
    atomicAdd(&g_deg[d], 1);
}

// ---------------- prefix sum ------------------------------------------------
__global__ void scanA(int N) {
    __shared__ int sm[256];
    int tid = threadIdx.x;
    int i = blockIdx.x * 256 + tid;
    int v = (i < N) ? g_deg[i] : 0;
    sm[tid] = v;
    __syncthreads();
    #pragma unroll
    for (int o = 1; o < 256; o <<= 1) {
        int t = (tid >= o) ? sm[tid - o] : 0;
        __syncthreads();
        sm[tid] += t;
        __syncthreads();
    }
    if (i < N) g_rowptr[i] = sm[tid] - v;
    if (tid == 255) g_bsum[blockIdx.x] = sm[255];
}

__global__ void scanB(int nb, int N, int Etot) {
    __shared__ int sm[512];
    int tid = threadIdx.x;
    int v = (tid < nb) ? g_bsum[tid] : 0;
    sm[tid] = v;
    __syncthreads();
    #pragma unroll
    for (int o = 1; o < 512; o <<= 1) {
        int t = (tid >= o) ? sm[tid - o] : 0;
        __syncthreads();
        sm[tid] += t;
        __syncthreads();
    }
    if (tid < nb) g_bsum[tid] = sm[tid] - v;
    if (tid == 0) g_rowptr[N] = Etot;
}

__global__ void scanC(int N) {
    int i = blockIdx.x * 256 + threadIdx.x;
    if (i < N) {
        int v = g_rowptr[i] + g_bsum[blockIdx.x];
        g_rowptr[i] = v;
        g_cur[i] = v;
    }
}

__global__ void scatter_kernel(const void* ei, int E, int N) {
    int e = blockIdx.x * blockDim.x + threadIdx.x;
    int tot = E + N;
    if (e >= tot) return;
    int s, d;
    if (e < E) {
        if (g_is64) {
            const long long* p = (const long long*)ei;
            s = (int)p[e];
            d = (int)p[(size_t)E + e];
        } else {
            const int* p = (const int*)ei;
            s = p[e];
            d = p[E + e];
        }
    } else {
        s = e - E; d = e - E;
    }
    int pos = atomicAdd(&g_cur[d], 1);
    g_esrc[pos] = s;
}

// ---------------- GEMM1 (tf32 HMMA): Round-10-exact version ------------------
// 256 threads = 8 warps; block tile 128 rows x 64 cols; warp tile 16x64.
__global__ void gemm1_tc(const float* __restrict__ x, const float* __restrict__ W, int N) {
    __shared__ float As[128][36];   // 144 B/row: 16B-aligned, +4 bank skew
    __shared__ float Bs[32][68];    // 272 B/row: 16B-aligned, +4 bank skew
    __shared__ float ws[FIN], wd[FIN];
    int tid = threadIdx.x;
    int warp = tid >> 5, lane = tid & 31;
    int row0 = blockIdx.x * 128;
    if (tid < FIN) { ws[tid] = g_ws[tid]; wd[tid] = g_wd[tid]; }

    float d[8][4] = {};
    float ssacc = 0.f, sdacc = 0.f;
    int sr = lane >> 1, sh = lane & 1;       // s-compute: 2 lanes per row

    for (int kt = 0; kt < FIN; kt += 32) {
        __syncthreads();                     // protect As/ws before (re)use
        #pragma unroll
        for (int i = 0; i < 4; i++) {        // stage A: 128 x 32
            int l = tid + i * 256;
            int rr = l >> 3, c4 = (l & 7) * 4;
            int node = row0 + rr;
            float4 v = make_float4(0.f, 0.f, 0.f, 0.f);
            if (node < N) v = *(const float4*)(x + (size_t)node * FIN + kt + c4);
            *(float4*)&As[rr][c4] = v;
        }
        #pragma unroll
        for (int i = 0; i < 2; i++) {        // stage B: 32 x 64
            int l = tid + i * 256;
            int kk = l >> 4, c4 = (l & 15) * 4;
            *(float4*)&Bs[kk][c4] = *(const float4*)(W + (size_t)(kt + kk) * HD1 + c4);
        }
        __syncthreads();

        #pragma unroll
        for (int ks = 0; ks < 4; ks++) {
            int k0 = ks * 8;
            int ar = warp * 16 + (lane >> 2);
            int ac = k0 + (lane & 3);
            uint32_t a0 = cvt_tf32(As[ar][ac]);
            uint32_t a1 = cvt_tf32(As[ar + 8][ac]);
            uint32_t a2 = cvt_tf32(As[ar][ac + 4]);
            uint32_t a3 = cvt_tf32(As[ar + 8][ac + 4]);
            #pragma unroll
            for (int nt = 0; nt < 8; nt++) {
                int bc = nt * 8 + (lane >> 2);
                uint32_t b0 = cvt_tf32(Bs[k0 + (lane & 3)][bc]);
                uint32_t b1 = cvt_tf32(Bs[k0 + (lane & 3) + 4][bc]);
                mma_tf32(d[nt], a0, a1, a2, a3, b0, b1);
            }
        }
        // exact fp32 s: s[row] += x[row, kt..kt+32) . ws/wd
        {
            const float* arow = As[warp * 16 + sr];
            #pragma unroll
            for (int k = 0; k < 16; k++) {
                float v = arow[sh * 16 + k];
                ssacc += v * ws[kt + sh * 16 + k];
                sdacc += v * wd[kt + sh * 16 + k];
            }
        }
    }

    // store h1 as fp16 (D frag: d0,d1 adjacent cols, rows g / g+8)
    int orow0 = row0 + warp * 16 + (lane >> 2);
    int orow1 = orow0 + 8;
    #pragma unroll
    for (int nt = 0; nt < 8; nt++) {
        int col = nt * 8 + (lane & 3) * 2;
        if (orow0 < N)
            *(__half2*)(g_h1h + (size_t)orow0 * HD1 + col) = __floats2half2_rn(d[nt][0], d[nt][1]);
        if (orow1 < N)
            *(__half2*)(g_h1h + (size_t)orow1 * HD1 + col) = __floats2half2_rn(d[nt][2], d[nt][3]);
    }
    // s reduce (2 lanes/row) + store
    ssacc += __shfl_down_sync(0xFFFFFFFFu, ssacc, 1);
    sdacc += __shfl_down_sync(0xFFFFFFFFu, sdacc, 1);
    if (sh == 0) {
        int node = row0 + warp * 16 + sr;
        if (node < N) { g_ssrc[node] = ssacc; g_sdst[node] = sdacc; }
    }
}

// ---------------- layer-1 gather: warp per dst, chunked shfl -----------------
__global__ void gather64(const float* __restrict__ b1, int N) {
    int gid = blockIdx.x * blockDim.x + threadIdx.x;
    int w = gid >> 5, lane = gid & 31;
    if (w >= N) return;
    int beg = g_rowptr[w], end = g_rowptr[w + 1];
    float sd = g_sdst[w];
    float2 acc = make_float2(0.f, 0.f);
    float z = 0.f;
    const __half2* h1v = (const __half2*)g_h1h;
    for (int base = beg; base < end; base += 32) {
        int i = base + lane;
        int my_s = 0; float my_p = 0.f;
        if (i < end) {
            my_s = __ldg(&g_esrc[i]);
            float e = __ldg(&g_ssrc[my_s]) + sd;
            e = e > 0.f ? e : 0.2f * e;
            my_p = __expf(e);
        }
        int cnt = min(32, end - base);
        for (int j = 0; j < cnt; j++) {
            int   s = __shfl_sync(0xFFFFFFFFu, my_s, j);
            float p = __shfl_sync(0xFFFFFFFFu, my_p, j);
            z += p;
            float2 hv = __half22float2(h1v[s * 32 + lane]);
            acc.x += p * hv.x;
            acc.y += p * hv.y;
        }
    }
    float inv = __fdividef(1.f, z);
    float2 bb = *(const float2*)(b1 + lane * 2);
    float2 o;
    o.x = fmaxf(acc.x * inv + bb.x, 0.f);
    o.y = fmaxf(acc.y * inv + bb.y, 0.f);
    *(float2*)(g_t1 + (size_t)w * HD1 + lane * 2) = o;
}

// ---------------- GEMM2: h2 = t1 @ W2 (+ fused s2, fp16 h2 out) --------------
__global__ void gemm2_kernel(const float* __restrict__ W2,
                             const float* __restrict__ a_src, const float* __restrict__ a_dst,
                             int N) {
    __shared__ float Os[128][65];
    __shared__ float Ws[64][17];
    int tid = threadIdx.x;                 // 128 threads
    int node0 = blockIdx.x * 128;
    for (int i = tid; i < HD1 * HD2; i += 128) Ws[i >> 4][i & 15] = W2[i];
    for (int i = tid; i < 128 * HD1; i += 128) {
        int r = i >> 6, k = i & 63;
        int node = node0 + r;
        Os[r][k] = (node < N) ? g_t1[(size_t)node * HD1 + k] : 0.f;
    }
    __syncthreads();
    int node = node0 + tid;
    if (node >= N) return;
    float acc[16] = {};
    #pragma unroll 4
    for (int k = 0; k < HD1; k++) {
        float v = Os[tid][k];
        #pragma unroll
        for (int j = 0; j < HD2; j++) acc[j] += v * Ws[k][j];
    }
    __half2* hp = (__half2*)(g_h2h + (size_t)node * HD2);
    #pragma unroll
    for (int j = 0; j < 8; j++) hp[j] = __floats2half2_rn(acc[2*j], acc[2*j+1]);
    float ss = 0.f, sdv = 0.f;
    #pragma unroll
    for (int j = 0; j < HD2; j++) {
        ss  += acc[j] * __ldg(&a_src[j]);
        sdv += acc[j] * __ldg(&a_dst[j]);
    }
    g_ssrc[node] = ss;
    g_sdst[node] = sdv;
}

// ---------------- layer-2 gather + classifier + log_softmax (fused) ----------
// 8 lanes per dst; per-section shfl masks (0xFF << section base).
__global__ void gather16_final(const float* __restrict__ b2, const float* __restrict__ Wc,
                               const float* __restrict__ bc, float* __restrict__ out, int N) {
    __shared__ float Wcs[HD2 * NCLS];
    __shared__ float bcs[NCLS];
    __shared__ float b2s[HD2];
    int tid = threadIdx.x;                 // 256 threads -> 32 dsts/block
    for (int i = tid; i < HD2 * NCLS; i += 256) Wcs[i] = Wc[i];
    if (tid < NCLS) bcs[tid] = bc[tid];
    if (tid < HD2) b2s[tid] = b2[tid];
    __syncthreads();

    int gid = blockIdx.x * 256 + tid;
    int d = gid >> 3, l = gid & 7;
    if (d >= N) return;
    int lane = tid & 31;
    unsigned mask = 0xFFu << (lane & ~7);  // this 8-lane section only
    int beg = g_rowptr[d], end = g_rowptr[d + 1];
    float sd = g_sdst[d];
    float2 acc = make_float2(0.f, 0.f);
    float z = 0.f;
    const __half2* h2v = (const __half2*)g_h2h;
    for (int base = beg; base < end; base += 8) {
        int i = base + l;
        int my_s = 0; float my_p = 0.f;
        if (i < end) {
            my_s = __ldg(&g_esrc[i]);
            float e = __ldg(&g_ssrc[my_s]) + sd;
            e = e > 0.f ? e : 0.2f * e;
            my_p = __expf(e);
        }
        int cnt = min(8, end - base);
        for (int j = 0; j < cnt; j++) {
            int   s = __shfl_sync(mask, my_s, j, 8);
            float p = __shfl_sync(mask, my_p, j, 8);
            z += p;
            float2 hv = __half22float2(h2v[s * 8 + l]);
            acc.x += p * hv.x;
            acc.y += p * hv.y;
        }
    }
    float inv = __fdividef(1.f, z);
    float h0 = acc.x * inv + b2s[l * 2];
    float h1 = acc.y * inv + b2s[l * 2 + 1];

    // partial logits for this lane's 2 features
    float pl[NCLS];
    #pragma unroll
    for (int c = 0; c < NCLS; c++)
        pl[c] = h0 * Wcs[(l * 2) * NCLS + c] + h1 * Wcs[(l * 2 + 1) * NCLS + c];
    // butterfly reduce across the 8-lane section
    #pragma unroll
    for (int o = 4; o; o >>= 1) {
        #pragma unroll
        for (int c = 0; c < NCLS; c++)
            pl[c] += __shfl_xor_sync(mask, pl[c], o, 8);
    }
    #pragma unroll
    for (int c = 0; c < NCLS; c++) pl[c] += bcs[c];
    float mx = pl[0];
    #pragma unroll
    for (int c = 1; c < NCLS; c++) mx = fmaxf(mx, pl[c]);
    float sum = 0.f;
    #pragma unroll
    for (int c = 0; c < NCLS; c++) sum += __expf(pl[c] - mx);
    float lse = mx + logf(sum);
    if (l < 5) {        // 5 lanes write float2 each (out rows are 40B, 8B-aligned)
        float2 o2v = make_float2(pl[l * 2] - lse, pl[l * 2 + 1] - lse);
        *(float2*)(out + (size_t)d * NCLS + l * 2) = o2v;
    }
}

// ---------------- launch -----------------------------------------------------
extern "C" void kernel_launch(void* const* d_in, const int* in_sizes, int n_in,
                              void* d_out, int out_size) {
    const float* x   = (const float*)d_in[0];
    const void*  ei  = d_in[1];
    const float* W1  = (const float*)d_in[2];
    const float* a1s = (const float*)d_in[3];
    const float* a1d = (const float*)d_in[4];
    const float* b1  = (const float*)d_in[5];
    const float* W2  = (const float*)d_in[6];
    const float* a2s = (const float*)d_in[7];
    const float* a2d = (const float*)d_in[8];
    const float* b2  = (const float*)d_in[9];
    const float* Wc  = (const float*)d_in[10];
    const float* bc  = (const float*)d_in[11];
    float* out = (float*)d_out;

    int N = in_sizes[0] / FIN;
    int E = in_sizes[1] / 2;
    int Etot = E + N;
    int NB = CDIV(N, 256);

    // edge prep + CSR (shared by both layers) + w-vectors
    prep_kernel<<<NB, 256>>>(ei, W1, a1s, a1d, E, N);
    deg_kernel<<<CDIV(E, 256), 256>>>(ei, E);
    scanA<<<NB, 256>>>(N);
    scanB<<<1, 512>>>(NB, N, Etot);
    scanC<<<NB, 256>>>(N);
    scatter_kernel<<<CDIV(Etot, 256), 256>>>(ei, E, N);

    // layer 1
    gemm1_tc<<<CDIV(N, 128), 256>>>(x, W1, N);
    gather64<<<CDIV(N * 32, 256), 256>>>(b1, N);

    // layer 2
    gemm2_kernel<<<CDIV(N, 128), 128>>>(W2, a2s, a2d, N);
    gather16_final<<<CDIV(N * 8, 256), 256>>>(b2, Wc, bc, out, N);
}